// round 7
// baseline (speedup 1.0000x reference)
#include <cuda_runtime.h>
#include <cuda_bf16.h>
#include <cstdint>

// ExpertCapacityBuffer: N tokens, TOP_K=2, 64 experts.
// capacity = ceil(1.25*N*2/64). Flat slot-major: f = slot*N + tok.
// rank(f) = #{g<f : expert(g)==expert(f)}; keep iff rank < capacity.
//
// Single fused kernel (grid co-resident, one global-flag barrier):
//  P1: per-tile histograms -> g_cnt (row r: slot0 of tile r; row nbt+r: slot1)
//  barrier: done-counter; last block scans rows -> g_off; releases g_ready
//  P2: re-match, warp-shfl exclusive scans, ranks, outputs (w, idx, mask)

#define NE   64
#define NEP  65              // padded row to kill smem bank conflicts
#define TPB  1024
#define EPT  1024
#define MAXROWS 4096
#define NCH  16

__device__ int g_cnt[MAXROWS][NE];
__device__ int g_off[MAXROWS][NE];
__device__ int g_done = 0;
__device__ int g_ready = 0;
__device__ int g_done2 = 0;

__device__ __forceinline__ int ld_acq(const int* p) {
    int v;
    asm volatile("ld.acquire.gpu.b32 %0, [%1];" : "=r"(v) : "l"(p) : "memory");
    return v;
}
__device__ __forceinline__ void st_rel(int* p, int v) {
    asm volatile("st.release.gpu.b32 [%0], %1;" :: "l"(p), "r"(v) : "memory");
}

__global__ void __launch_bounds__(TPB, 1)
k_fused(const float* __restrict__ w, const void* __restrict__ eraw,
        int n_tok, int capacity, int nbt,
        float* __restrict__ out_w, void* __restrict__ out_idx, int idx_mode,
        float* __restrict__ out_mask) {
    __shared__ int hA[32][NEP];
    __shared__ int hB[32][NEP];
    __shared__ int offA[NE], offB[NE];
    __shared__ int s_is64, s_last;
    const int t = threadIdx.x;
    const int warp = t >> 5, lane = t & 31;
    const unsigned lt = (1u << lane) - 1u;

    // dtype probe (warp 0): int64 values <64 => odd 32-bit words zero
    if (t < 32) {
        unsigned x = ((const unsigned*)eraw)[2 * lane + 1];
        unsigned nz = __ballot_sync(0xFFFFFFFFu, x != 0u);
        if (lane == 0) s_is64 = (nz == 0u);
    }

    // ---------------- Phase 1: histograms ----------------
    for (int tile = blockIdx.x; tile < nbt; tile += gridDim.x) {
        const int tok = tile * EPT + t;
        const bool valid = tok < n_tok;
        int2 v32 = make_int2(0, 0);
        if (valid) v32 = __ldg((const int2*)eraw + tok);

        for (int i = t; i < 32 * NEP; i += TPB) { ((int*)hA)[i] = 0; ((int*)hB)[i] = 0; }
        __syncthreads();

        int e0 = NE + lane, e1 = NE + lane;     // unique keys for invalid lanes
        if (valid) {
            if (s_is64) {
                longlong2 v = __ldg((const longlong2*)eraw + tok);
                e0 = (int)v.x & (NE - 1); e1 = (int)v.y & (NE - 1);
            } else {
                e0 = v32.x & (NE - 1); e1 = v32.y & (NE - 1);
            }
        }
        unsigned m0 = __match_any_sync(0xFFFFFFFFu, e0);
        unsigned m1 = __match_any_sync(0xFFFFFFFFu, e1);
        if (valid && !(m0 & lt)) hA[warp][e0] = __popc(m0);
        if (valid && !(m1 & lt)) hB[warp][e1] = __popc(m1);
        __syncthreads();

        // warp-shfl reductions: warp handles pairs p = warp*4+k (128 expert-slot pairs)
        #pragma unroll
        for (int k = 0; k < 4; k++) {
            const int p = warp * 4 + k;
            const int e = p & (NE - 1);
            const bool isB = p >= NE;
            int v = isB ? hB[lane][e] : hA[lane][e];
            #pragma unroll
            for (int d = 16; d > 0; d >>= 1) v += __shfl_xor_sync(0xFFFFFFFFu, v, d);
            if (lane == 0) g_cnt[isB ? (nbt + tile) : tile][e] = v;
        }
        __syncthreads();
    }

    // ---------------- Grid barrier + global scan ----------------
    if (t == 0) {
        __threadfence();
        s_last = (atomicAdd(&g_done, 1) == (int)gridDim.x - 1);
    }
    __syncthreads();

    if (s_last) {
        __threadfence();                       // acquire all g_cnt
        const int rows = 2 * nbt;
        const int e = t & (NE - 1), c = t >> 6;
        const int rpc = (rows + NCH - 1) / NCH;
        const int r0 = c * rpc;
        __shared__ int part[NCH][NE];

        if (rpc <= 16) {
            int vals[16];
            #pragma unroll
            for (int i = 0; i < 16; i++) {
                int r = r0 + i;
                vals[i] = (i < rpc && r < rows) ? g_cnt[r][e] : 0;
            }
            int s = 0;
            #pragma unroll
            for (int i = 0; i < 16; i++) s += vals[i];
            part[c][e] = s;
            __syncthreads();
            if (t < NE) {
                int run = 0;
                #pragma unroll
                for (int cc = 0; cc < NCH; cc++) { int v = part[cc][t]; part[cc][t] = run; run += v; }
            }
            __syncthreads();
            int run = part[c][e];
            #pragma unroll
            for (int i = 0; i < 16; i++) {
                int r = r0 + i;
                if (i < rpc && r < rows) { g_off[r][e] = run; run += vals[i]; }
            }
        } else {
            int s = 0;
            for (int r = r0; r < min(r0 + rpc, rows); r++) s += g_cnt[r][e];
            part[c][e] = s;
            __syncthreads();
            if (t < NE) {
                int run = 0;
                #pragma unroll
                for (int cc = 0; cc < NCH; cc++) { int v = part[cc][t]; part[cc][t] = run; run += v; }
            }
            __syncthreads();
            int run = part[c][e];
            for (int r = r0; r < min(r0 + rpc, rows); r++) { int v = g_cnt[r][e]; g_off[r][e] = run; run += v; }
        }
        __syncthreads();
        if (t == 0) { __threadfence(); st_rel(&g_ready, 1); }
    }

    if (t == 0) { while (ld_acq(&g_ready) == 0) { } }
    __syncthreads();

    // ---------------- Phase 2: ranks + outputs ----------------
    for (int tile = blockIdx.x; tile < nbt; tile += gridDim.x) {
        const int tok = tile * EPT + t;
        const bool valid = tok < n_tok;
        int2 v32 = make_int2(0, 0);
        float2 wv = make_float2(0.f, 0.f);
        if (valid) {
            v32 = __ldg((const int2*)eraw + tok);
            wv  = __ldg((const float2*)w + tok);
        }
        if (t < NE)          offA[t] = g_off[tile][t];
        else if (t < 2 * NE) offB[t - NE] = g_off[nbt + tile][t - NE];
        for (int i = t; i < 32 * NEP; i += TPB) { ((int*)hA)[i] = 0; ((int*)hB)[i] = 0; }
        __syncthreads();

        int e0 = NE + lane, e1 = NE + lane;
        if (valid) {
            if (s_is64) {
                longlong2 v = __ldg((const longlong2*)eraw + tok);
                e0 = (int)v.x & (NE - 1); e1 = (int)v.y & (NE - 1);
            } else {
                e0 = v32.x & (NE - 1); e1 = v32.y & (NE - 1);
            }
        }
        unsigned m0 = __match_any_sync(0xFFFFFFFFu, e0);
        unsigned m1 = __match_any_sync(0xFFFFFFFFu, e1);
        const int wr0 = __popc(m0 & lt), wr1 = __popc(m1 & lt);
        if (valid && wr0 == 0) hA[warp][e0] = __popc(m0);
        if (valid && wr1 == 0) hB[warp][e1] = __popc(m1);
        __syncthreads();

        // warp-shfl EXCLUSIVE scans over the 32 warp-rows, 4 pairs per warp
        #pragma unroll
        for (int k = 0; k < 4; k++) {
            const int p = warp * 4 + k;
            const int e = p & (NE - 1);
            const bool isB = p >= NE;
            int v = isB ? hB[lane][e] : hA[lane][e];
            int x = v;
            #pragma unroll
            for (int d = 1; d < 32; d <<= 1) {
                int y = __shfl_up_sync(0xFFFFFFFFu, x, d);
                if (lane >= d) x += y;
            }
            if (isB) hB[lane][e] = x - v; else hA[lane][e] = x - v;
        }
        __syncthreads();

        if (valid) {
            const int rank0 = offA[e0] + hA[warp][e0] + wr0;
            const int rank1 = offB[e1] + hB[warp][e1] + wr1;
            const float w0 = (rank0 < capacity) ? wv.x : 0.0f;
            const float w1 = (rank1 < capacity) ? wv.y : 0.0f;
            ((float2*)out_w)[tok] = make_float2(w0, w1);
            if (idx_mode == 1) {
                ((float2*)out_idx)[tok] = make_float2((float)e0, (float)e1);
            } else if (idx_mode == 2) {
                longlong2 iv; iv.x = e0; iv.y = e1;
                ((longlong2*)out_idx)[tok] = iv;
            }
            if (out_mask) out_mask[tok] = ((w0 + w1) == 0.0f) ? 1.0f : 0.0f;
        }
        __syncthreads();
    }

    // reset counters for next graph replay (last block to get here)
    if (t == 0) {
        if (atomicAdd(&g_done2, 1) == (int)gridDim.x - 1) {
            g_done = 0; g_ready = 0; g_done2 = 0;
        }
    }
}

extern "C" void kernel_launch(void* const* d_in, const int* in_sizes, int n_in,
                              void* d_out, int out_size) {
    const float* w    = (const float*)d_in[0];
    const void*  eidx = d_in[1];

    int flat  = in_sizes[0];                 // N * TOP_K
    int n_tok = flat / 2;
    int capacity = (flat * 5 + 255) / 256;   // ceil(1.25 * flat / 64)
    if (capacity < 1) capacity = 1;
    int nbt = (n_tok + EPT - 1) / EPT;
    if (2 * nbt > MAXROWS) nbt = MAXROWS / 2;   // guard (not hit at these sizes)
    int grid = (nbt < 132) ? nbt : 132;         // co-resident single wave (<=148 SMs)

    float* out = (float*)d_out;
    float* out_w    = out;
    void*  out_idx  = nullptr;
    float* out_mask = nullptr;
    int idx_mode = 0;

    if (out_size >= 3 * flat + n_tok) {          // weights + i64 indices + mask
        idx_mode = 2; out_idx = out + flat; out_mask = out + 3 * flat;
    } else if (out_size >= 2 * flat + n_tok) {   // weights + 1-word indices + mask
        idx_mode = 1; out_idx = out + flat; out_mask = out + 2 * flat;
    } else if (out_size >= flat + n_tok) {       // weights + mask
        out_mask = out + flat;
    }

    k_fused<<<grid, TPB>>>(w, eidx, n_tok, capacity, nbt,
                           out_w, out_idx, idx_mode, out_mask);
}

// round 8
// speedup vs baseline: 1.1361x; 1.1361x over previous
#include <cuda_runtime.h>
#include <cuda_bf16.h>
#include <cstdint>

// ExpertCapacityBuffer: N tokens, TOP_K=2, 64 experts.
// capacity = ceil(1.25*N*2/64). Flat slot-major: f = slot*N + tok.
// rank(f) = #{g<f : expert(g)==expert(f)}; keep iff rank < capacity.
//
// g_cnt rows: row r in [0,nbt) = slot0 of token-block r; row nbt+r = slot1.
// Row-major row order == flat order.
// Kernel 1 (count): per-row histograms (warp-shfl column reduce).
// Kernel 2 (apply): MLP-16 redundant prefix over g_cnt + shfl scans + outputs.

#define NE   64
#define NEP  65              // padded row kills smem bank conflicts
#define TPB  1024
#define EPT  1024
#define MAXROWS 4096

__device__ int g_cnt[MAXROWS][NE];

// warp-0 dtype probe: int64 values <64 => odd 32-bit words zero (first 256B).
__device__ __forceinline__ void probe_w0(const void* eraw, int lane, int* s_is64) {
    if (threadIdx.x < 32) {
        unsigned x = ((const unsigned*)eraw)[2 * lane + 1];
        unsigned nz = __ballot_sync(0xFFFFFFFFu, x != 0u);
        if (lane == 0) *s_is64 = (nz == 0u);
    }
}

// ---------------- Kernel 1: per-row expert histograms ----------------
__global__ void __launch_bounds__(TPB)
k_count(const void* __restrict__ eraw, int n_tok, int nbt) {
    __shared__ int hA[32][NEP];
    __shared__ int hB[32][NEP];
    __shared__ int s_is64;
    const int t = threadIdx.x, b = blockIdx.x;
    const int warp = t >> 5, lane = t & 31;
    const unsigned lt = (1u << lane) - 1u;

    const int tok = b * EPT + t;
    const bool valid = tok < n_tok;

    int2 v32 = make_int2(0, 0);
    if (valid) v32 = __ldg((const int2*)eraw + tok);      // eager

    for (int i = t; i < 32 * NEP; i += TPB) { ((int*)hA)[i] = 0; ((int*)hB)[i] = 0; }
    probe_w0(eraw, lane, &s_is64);
    __syncthreads();

    int e0 = NE + lane, e1 = NE + lane;                    // unique keys if invalid
    if (valid) {
        if (s_is64) {
            longlong2 v = __ldg((const longlong2*)eraw + tok);
            e0 = (int)v.x & (NE - 1); e1 = (int)v.y & (NE - 1);
        } else {
            e0 = v32.x & (NE - 1); e1 = v32.y & (NE - 1);
        }
    }
    unsigned m0 = __match_any_sync(0xFFFFFFFFu, e0);
    unsigned m1 = __match_any_sync(0xFFFFFFFFu, e1);
    if (valid && !(m0 & lt)) hA[warp][e0] = __popc(m0);
    if (valid && !(m1 & lt)) hB[warp][e1] = __popc(m1);
    __syncthreads();

    // warp-shfl column reduction: warp handles pairs p = warp*4+k
    #pragma unroll
    for (int k = 0; k < 4; k++) {
        const int p = warp * 4 + k;
        const int e = p & (NE - 1);
        const bool isB = p >= NE;
        int v = isB ? hB[lane][e] : hA[lane][e];
        #pragma unroll
        for (int d = 16; d > 0; d >>= 1) v += __shfl_xor_sync(0xFFFFFFFFu, v, d);
        if (lane == 0) g_cnt[isB ? (nbt + b) : b][e] = v;
    }
}

// ---------------- Kernel 2: prefix + ranks + outputs ----------------
// idx_mode: 0 none, 1 one-word (float), 2 int64
__global__ void __launch_bounds__(TPB)
k_apply(const float* __restrict__ w, const void* __restrict__ eraw,
        int n_tok, int capacity, int nbt,
        float* __restrict__ out_w, void* __restrict__ out_idx, int idx_mode,
        float* __restrict__ out_mask) {
    __shared__ int hA[32][NEP];
    __shared__ int hB[32][NEP];
    __shared__ int partA[16][NE];
    __shared__ int partB[16][NE];
    __shared__ int offA[NE], offB[NE];
    __shared__ int s_is64;
    const int t = threadIdx.x, b = blockIdx.x;
    const int warp = t >> 5, lane = t & 31;
    const unsigned lt = (1u << lane) - 1u;

    const int tok = b * EPT + t;
    const bool valid = tok < n_tok;

    // eager data loads
    int2 v32 = make_int2(0, 0);
    float2 wv = make_float2(0.f, 0.f);
    if (valid) {
        v32 = __ldg((const int2*)eraw + tok);
        wv  = __ldg((const float2*)w + tok);
    }

    // eager MLP-16 prefix over g_cnt rows. Static array => loads always
    // in-bounds; predicate only the accumulation.
    {
        const int e = t & (NE - 1), c = t >> 6;      // 16 chunks x 64 experts
        const int limA = b, limB = nbt + b;          // rows < lim contribute
        int accA = 0, accB = 0;
        if (2 * nbt <= 256) {                        // fast path (nbt <= 128)
            int vals[16];
            #pragma unroll
            for (int i = 0; i < 16; i++) vals[i] = g_cnt[c + 16 * i][e];
            #pragma unroll
            for (int i = 0; i < 16; i++) {
                int r = c + 16 * i;
                if (r < limB) accB += vals[i];
                if (r < limA) accA += vals[i];
            }
        } else {                                     // generic fallback
            for (int r = c; r < limB; r += 16) {
                int v = g_cnt[r][e];
                accB += v;
                if (r < limA) accA += v;
            }
        }
        partA[c][e] = accA;
        partB[c][e] = accB;
    }

    for (int i = t; i < 32 * NEP; i += TPB) { ((int*)hA)[i] = 0; ((int*)hB)[i] = 0; }
    probe_w0(eraw, lane, &s_is64);
    __syncthreads();

    int e0 = NE + lane, e1 = NE + lane;
    if (valid) {
        if (s_is64) {
            longlong2 v = __ldg((const longlong2*)eraw + tok);
            e0 = (int)v.x & (NE - 1); e1 = (int)v.y & (NE - 1);
        } else {
            e0 = v32.x & (NE - 1); e1 = v32.y & (NE - 1);
        }
    }
    unsigned m0 = __match_any_sync(0xFFFFFFFFu, e0);
    unsigned m1 = __match_any_sync(0xFFFFFFFFu, e1);
    const int wr0 = __popc(m0 & lt), wr1 = __popc(m1 & lt);
    if (valid && wr0 == 0) hA[warp][e0] = __popc(m0);
    if (valid && wr1 == 0) hB[warp][e1] = __popc(m1);
    __syncthreads();

    // warp-shfl exclusive scans over the 32 warp-rows; plus chunk-part reduce
    #pragma unroll
    for (int k = 0; k < 4; k++) {
        const int p = warp * 4 + k;
        const int e = p & (NE - 1);
        const bool isB = p >= NE;
        int v = isB ? hB[lane][e] : hA[lane][e];
        int x = v;
        #pragma unroll
        for (int d = 1; d < 32; d <<= 1) {
            int y = __shfl_up_sync(0xFFFFFFFFu, x, d);
            if (lane >= d) x += y;
        }
        if (isB) hB[lane][e] = x - v; else hA[lane][e] = x - v;
        // fold 16 chunk partials (lanes 0..15 load, reduce within half-warp)
        int pv = (lane < 16) ? (isB ? partB[lane][e] : partA[lane][e]) : 0;
        #pragma unroll
        for (int d = 8; d > 0; d >>= 1) pv += __shfl_xor_sync(0xFFFFFFFFu, pv, d);
        if (lane == 0) { if (isB) offB[e] = pv; else offA[e] = pv; }
    }
    __syncthreads();

    if (valid) {
        const int rank0 = offA[e0] + hA[warp][e0] + wr0;
        const int rank1 = offB[e1] + hB[warp][e1] + wr1;
        const float w0 = (rank0 < capacity) ? wv.x : 0.0f;
        const float w1 = (rank1 < capacity) ? wv.y : 0.0f;
        ((float2*)out_w)[tok] = make_float2(w0, w1);
        if (idx_mode == 1) {
            ((float2*)out_idx)[tok] = make_float2((float)e0, (float)e1);
        } else if (idx_mode == 2) {
            longlong2 iv; iv.x = e0; iv.y = e1;
            ((longlong2*)out_idx)[tok] = iv;
        }
        if (out_mask) out_mask[tok] = ((w0 + w1) == 0.0f) ? 1.0f : 0.0f;
    }
}

extern "C" void kernel_launch(void* const* d_in, const int* in_sizes, int n_in,
                              void* d_out, int out_size) {
    const float* w    = (const float*)d_in[0];
    const void*  eidx = d_in[1];

    int flat  = in_sizes[0];                 // N * TOP_K
    int n_tok = flat / 2;
    int capacity = (flat * 5 + 255) / 256;   // ceil(1.25 * flat / 64)
    if (capacity < 1) capacity = 1;
    int nbt = (n_tok + EPT - 1) / EPT;
    if (2 * nbt > MAXROWS) nbt = MAXROWS / 2;   // guard (not hit at these sizes)

    float* out = (float*)d_out;
    float* out_w    = out;
    void*  out_idx  = nullptr;
    float* out_mask = nullptr;
    int idx_mode = 0;

    if (out_size >= 3 * flat + n_tok) {          // weights + i64 indices + mask
        idx_mode = 2; out_idx = out + flat; out_mask = out + 3 * flat;
    } else if (out_size >= 2 * flat + n_tok) {   // weights + 1-word indices + mask
        idx_mode = 1; out_idx = out + flat; out_mask = out + 2 * flat;
    } else if (out_size >= flat + n_tok) {       // weights + mask
        out_mask = out + flat;
    }

    k_count<<<nbt, TPB>>>(eidx, n_tok, nbt);
    k_apply<<<nbt, TPB>>>(w, eidx, n_tok, capacity, nbt,
                          out_w, out_idx, idx_mode, out_mask);
}